// round 3
// baseline (speedup 1.0000x reference)
#include <cuda_runtime.h>
#include <cstdint>
#include <cstddef>

#define C 128
#define CC (C * C)
#define NU 100000
#define NI 200000
#define NEDGE 1500000

// ---------------------------------------------------------------------------
// Scratch (device globals; no runtime allocation allowed)
// ---------------------------------------------------------------------------
__device__ __align__(256) float g_xu[2][(size_t)NU * C];
__device__ __align__(256) float g_xi[2][(size_t)NI * C];
__device__ __align__(256) int   g_cnt_u[NU];
__device__ __align__(256) int   g_cnt_i[NI];
__device__ __align__(256) int   g_off_u[NU + 1];
__device__ __align__(256) int   g_off_i[NI + 1];
__device__ __align__(256) int   g_cur_u[NU];
__device__ __align__(256) int   g_cur_i[NI];
__device__ __align__(256) int   g_csr_ui[NEDGE];  // src(user) ids grouped by dst item
__device__ __align__(256) int   g_csr_iu[NEDGE];  // src(item) ids grouped by dst user
__device__ __align__(256) int   g_bsum[256];

// ---------------------------------------------------------------------------
// f32x2 helpers (Blackwell packed fp32: 2x FFMA throughput vs 3-reg FFMA)
// ---------------------------------------------------------------------------
__device__ __forceinline__ unsigned long long pack2(float x, float y) {
    unsigned long long r;
    asm("mov.b64 %0, {%1, %2};" : "=l"(r) : "f"(x), "f"(y));
    return r;
}
__device__ __forceinline__ void unpack2(unsigned long long v, float& x, float& y) {
    asm("mov.b64 {%0, %1}, %2;" : "=f"(x), "=f"(y) : "l"(v));
}
__device__ __forceinline__ void ffma2(unsigned long long& d, unsigned long long a,
                                      unsigned long long b) {
    asm("fma.rn.f32x2 %0, %1, %2, %0;" : "+l"(d) : "l"(a), "l"(b));
}
__device__ __forceinline__ float f4get(float4 v, int i) {
    return i == 0 ? v.x : (i == 1 ? v.y : (i == 2 ? v.z : v.w));
}
__device__ __forceinline__ void add4(float4& a, float4 b) {
    a.x += b.x; a.y += b.y; a.z += b.z; a.w += b.w;
}

// Shared-memory strides (pad 132 floats: 16B-aligned rows, reduced conflicts)
#define SROW 132
#define UPD_SMEM_FLOATS (256 * SROW + 128 * SROW)
#define TE_SMEM_FLOATS  (128 * SROW * 2 + 128 + 64)

// One 128-wide K phase: acc[8][4] += In[node][k] * Wt[k][chan]
__device__ __forceinline__ void mac_phase(const float* sW, const float* sIn,
                                          int ng8, int c0,
                                          unsigned long long acc[8][4]) {
#pragma unroll 1
    for (int kc = 0; kc < 128; kc += 4) {
        float4 a4[8];
#pragma unroll
        for (int r = 0; r < 8; ++r)
            a4[r] = *(const float4*)(sIn + (ng8 + r) * SROW + kc);
#pragma unroll
        for (int kk = 0; kk < 4; ++kk) {
            const float* wr = sW + (kc + kk) * SROW + c0;
            ulonglong2 w01 = *(const ulonglong2*)(wr);
            ulonglong2 w23 = *(const ulonglong2*)(wr + 4);
#pragma unroll
            for (int r = 0; r < 8; ++r) {
                float av = f4get(a4[r], kk);
                unsigned long long a2 = pack2(av, av);
                ffma2(acc[r][0], a2, w01.x);
                ffma2(acc[r][1], a2, w01.y);
                ffma2(acc[r][2], a2, w23.x);
                ffma2(acc[r][3], a2, w23.y);
            }
        }
    }
}

// ---------------------------------------------------------------------------
// CSR build kernels
// ---------------------------------------------------------------------------
__global__ void zero_int_kernel(int4* __restrict__ p, int n4) {
    int stride = gridDim.x * blockDim.x;
    for (int i = blockIdx.x * blockDim.x + threadIdx.x; i < n4; i += stride)
        p[i] = make_int4(0, 0, 0, 0);
}

__global__ void count_kernel(const int* __restrict__ dst, int* __restrict__ cnt, int nE) {
    int stride = gridDim.x * blockDim.x;
    for (int i = blockIdx.x * blockDim.x + threadIdx.x; i < nE; i += stride)
        atomicAdd(cnt + __ldg(dst + i), 1);
}

#define SCAN_CHUNK 2048  // 256 threads x 8 elements

__global__ void scan_pass1(const int* __restrict__ cnt, int* __restrict__ bsum, int n) {
    __shared__ int sh[256];
    int tid = threadIdx.x;
    int base = blockIdx.x * SCAN_CHUNK + tid * 8;
    int s = 0;
#pragma unroll
    for (int j = 0; j < 8; ++j) {
        int idx = base + j;
        if (idx < n) s += cnt[idx];
    }
    sh[tid] = s;
    __syncthreads();
    for (int m = 128; m > 0; m >>= 1) {
        if (tid < m) sh[tid] += sh[tid + m];
        __syncthreads();
    }
    if (tid == 0) bsum[blockIdx.x] = sh[0];
}

__global__ void scan_pass2(int* __restrict__ bsum, int nb) {
    if (threadIdx.x == 0 && blockIdx.x == 0) {
        int acc = 0;
        for (int i = 0; i < nb; ++i) {
            int v = bsum[i];
            bsum[i] = acc;
            acc += v;
        }
    }
}

__global__ void scan_pass3(const int* __restrict__ cnt, const int* __restrict__ bsum,
                           int* __restrict__ off, int* __restrict__ cur, int n) {
    __shared__ int wsum[8];
    int tid = threadIdx.x;
    int lane = tid & 31, wrp = tid >> 5;
    int base = blockIdx.x * SCAN_CHUNK + tid * 8;

    int val[8], loc[8];
    int s = 0;
#pragma unroll
    for (int j = 0; j < 8; ++j) {
        int idx = base + j;
        val[j] = (idx < n) ? cnt[idx] : 0;
        loc[j] = s;
        s += val[j];
    }
    // warp inclusive scan of per-thread sums
    int incl = s;
#pragma unroll
    for (int m = 1; m < 32; m <<= 1) {
        int t = __shfl_up_sync(0xffffffffu, incl, m);
        if (lane >= m) incl += t;
    }
    if (lane == 31) wsum[wrp] = incl;
    __syncthreads();
    if (tid == 0) {
        int acc = 0;
#pragma unroll
        for (int i = 0; i < 8; ++i) {
            int t = wsum[i];
            wsum[i] = acc;
            acc += t;
        }
    }
    __syncthreads();
    int excl = incl - s + wsum[wrp];
    int boff = bsum[blockIdx.x];
#pragma unroll
    for (int j = 0; j < 8; ++j) {
        int idx = base + j;
        if (idx < n) {
            int o = boff + excl + loc[j];
            off[idx] = o;
            cur[idx] = o;
            if (idx == n - 1) off[n] = o + val[j];
        }
    }
}

__global__ void fill_kernel(const int* __restrict__ src, const int* __restrict__ dst,
                            int* __restrict__ cur, int* __restrict__ csr, int nE) {
    int stride = gridDim.x * blockDim.x;
    for (int i = blockIdx.x * blockDim.x + threadIdx.x; i < nE; i += stride) {
        int d = __ldg(dst + i);
        int p = atomicAdd(cur + d, 1);
        csr[p] = __ldg(src + i);
    }
}

// ---------------------------------------------------------------------------
// Temporal encoder: out = x + PE(rel_time) @ W^T + b
// ---------------------------------------------------------------------------
__global__ __launch_bounds__(256, 1)
void temporal_kernel(const float* __restrict__ x, const int* __restrict__ seed_time,
                     const int* __restrict__ node_time, const int* __restrict__ batch,
                     const float* __restrict__ W, const float* __restrict__ bias,
                     float* __restrict__ out, int n_nodes) {
    extern __shared__ float smem[];
    float* sW   = smem;                    // [128][SROW]
    float* sPE  = smem + 128 * SROW;       // [128][SROW]
    float* sRel = sPE + 128 * SROW;        // [128]
    float* sDiv = sRel + 128;              // [64]

    int tid = threadIdx.x;
    int cg = tid & 15, ng = tid >> 4;
    int c0 = cg * 8, ng8 = ng * 8;

    for (int i = tid; i < CC; i += 256) {
        int c = i >> 7, k = i & 127;
        sW[k * SROW + c] = W[i];
    }
    if (tid < 64)
        sDiv[tid] = exp2f(-(float)tid * 0.20762050593046015f);  // 10000^(-j/64)

    unsigned long long bias2[4];
#pragma unroll
    for (int p = 0; p < 4; ++p)
        bias2[p] = pack2(__ldg(bias + c0 + 2 * p), __ldg(bias + c0 + 2 * p + 1));
    __syncthreads();

    int ntiles = (n_nodes + 127) >> 7;
    for (int t = blockIdx.x; t < ntiles; t += gridDim.x) {
        int t0 = t << 7;
        int valid = min(128, n_nodes - t0);
        __syncthreads();

        if (tid < 128) {
            float r = 0.f;
            int n = t0 + tid;
            if (tid < valid) {
                int st = __ldg(seed_time + __ldg(batch + n));
                r = (float)(st - __ldg(node_time + n)) * (1.0f / 86400.0f);
            }
            sRel[tid] = r;
        }
        __syncthreads();

        for (int i = tid; i < 128 * 64; i += 256) {
            int n = i >> 6, j = i & 63;
            float ang = sRel[n] * sDiv[j];
            float kq = rintf(ang * 0.15915494309189535f);
            ang = fmaf(kq, -6.283185307179586f, ang);
            float sv, cv;
            sincosf(ang, &sv, &cv);
            sPE[n * SROW + 2 * j]     = sv;
            sPE[n * SROW + 2 * j + 1] = cv;
        }
        __syncthreads();

        unsigned long long acc[8][4];
#pragma unroll
        for (int r = 0; r < 8; ++r)
#pragma unroll
            for (int p = 0; p < 4; ++p) acc[r][p] = bias2[p];

        mac_phase(sW, sPE, ng8, c0, acc);

#pragma unroll
        for (int r = 0; r < 8; ++r) {
            int n = ng8 + r;
            if (n < valid) {
                float v[8];
#pragma unroll
                for (int p = 0; p < 4; ++p) unpack2(acc[r][p], v[2 * p], v[2 * p + 1]);
                const float* px = x + (size_t)(t0 + n) * C + c0;
                float4 x0 = __ldg((const float4*)px);
                float4 x1 = __ldg((const float4*)px + 1);
                float* po = out + (size_t)(t0 + n) * C + c0;
                *(float4*)po = make_float4(v[0] + x0.x, v[1] + x0.y, v[2] + x0.z, v[3] + x0.w);
                *(float4*)(po + 4) = make_float4(v[4] + x1.x, v[5] + x1.y, v[6] + x1.z, v[7] + x1.w);
            }
        }
    }
}

// ---------------------------------------------------------------------------
// Fused layer update:
//   out = relu(LN( mean_gather(x_src, csr, off) @ Wl^T + bias + xin @ Wr^T ))
// Gather-reduce happens directly into smem (no msg buffer, no atomics).
// ---------------------------------------------------------------------------
__global__ __launch_bounds__(256, 1)
void update_kernel(const float* __restrict__ x_src, const int* __restrict__ csr,
                   const int* __restrict__ off,
                   const float* __restrict__ xin,
                   const float* __restrict__ Wl, const float* __restrict__ Wr,
                   const float* __restrict__ bias,
                   const float* __restrict__ lng, const float* __restrict__ lnb,
                   float* __restrict__ out, int n_nodes) {
    extern __shared__ float smem[];
    float* sW  = smem;               // [256][SROW]: rows 0..127 = Wl^T, 128..255 = Wr^T
    float* sIn = smem + 256 * SROW;  // [128][SROW]

    int tid = threadIdx.x;
    int lane = tid & 31, wrp = tid >> 5;
    int cg = tid & 15, ng = tid >> 4;
    int c0 = cg * 8, ng8 = ng * 8;

    for (int i = tid; i < CC; i += 256) {
        int c = i >> 7, k = i & 127;
        sW[k * SROW + c]         = Wl[i];
        sW[(128 + k) * SROW + c] = Wr[i];
    }
    float gv[8], bv[8];
    unsigned long long bias2[4];
#pragma unroll
    for (int j = 0; j < 8; ++j) {
        gv[j] = __ldg(lng + c0 + j);
        bv[j] = __ldg(lnb + c0 + j);
    }
#pragma unroll
    for (int p = 0; p < 4; ++p)
        bias2[p] = pack2(__ldg(bias + c0 + 2 * p), __ldg(bias + c0 + 2 * p + 1));
    __syncthreads();

    int ntiles = (n_nodes + 127) >> 7;
    for (int t = blockIdx.x; t < ntiles; t += gridDim.x) {
        int t0 = t << 7;
        int valid = min(128, n_nodes - t0);

        unsigned long long acc[8][4];
#pragma unroll
        for (int r = 0; r < 8; ++r)
#pragma unroll
            for (int p = 0; p < 4; ++p) acc[r][p] = bias2[p];

        // --- phase 0: gather-mean of neighbor features into sIn ---
        // warp 'wrp' handles the 16 consecutive tile rows [wrp*16, wrp*16+16)
#pragma unroll 1
        for (int ni = 0; ni < 16; ++ni) {
            int n = wrp * 16 + ni;
            float4 a0 = make_float4(0.f, 0.f, 0.f, 0.f);
            float4 a1 = a0, a2 = a0, a3 = a0;
            int deg = 0;
            if (n < valid) {
                int node = t0 + n;
                int o0 = __ldg(off + node);
                int o1 = __ldg(off + node + 1);
                deg = o1 - o0;
                int k = o0;
                for (; k + 4 <= o1; k += 4) {
                    int s0 = __ldg(csr + k);
                    int s1 = __ldg(csr + k + 1);
                    int s2 = __ldg(csr + k + 2);
                    int s3 = __ldg(csr + k + 3);
                    add4(a0, __ldg((const float4*)(x_src + (size_t)s0 * C) + lane));
                    add4(a1, __ldg((const float4*)(x_src + (size_t)s1 * C) + lane));
                    add4(a2, __ldg((const float4*)(x_src + (size_t)s2 * C) + lane));
                    add4(a3, __ldg((const float4*)(x_src + (size_t)s3 * C) + lane));
                }
                for (; k < o1; ++k) {
                    int s0 = __ldg(csr + k);
                    add4(a0, __ldg((const float4*)(x_src + (size_t)s0 * C) + lane));
                }
            }
            add4(a0, a1); add4(a2, a3); add4(a0, a2);
            float invd = 1.0f / (float)max(deg, 1);
            a0.x *= invd; a0.y *= invd; a0.z *= invd; a0.w *= invd;
            *(float4*)(sIn + n * SROW + lane * 4) = a0;
        }
        __syncthreads();
        mac_phase(sW, sIn, ng8, c0, acc);
        __syncthreads();

        // --- phase 1: self features ---
        for (int i = tid; i < 128 * 32; i += 256) {
            int n = i >> 5, c4 = (i & 31) << 2;
            float4 v = make_float4(0.f, 0.f, 0.f, 0.f);
            if (n < valid)
                v = __ldg((const float4*)(xin + (size_t)(t0 + n) * C + c4));
            *(float4*)(sIn + n * SROW + c4) = v;
        }
        __syncthreads();
        mac_phase(sW + 128 * SROW, sIn, ng8, c0, acc);
        __syncthreads();

        // --- epilogue: LayerNorm (reduce across 16 channel-group lanes) + ReLU ---
#pragma unroll
        for (int r = 0; r < 8; ++r) {
            float v[8];
#pragma unroll
            for (int p = 0; p < 4; ++p) unpack2(acc[r][p], v[2 * p], v[2 * p + 1]);
            float s = 0.f, q = 0.f;
#pragma unroll
            for (int j = 0; j < 8; ++j) { s += v[j]; q += v[j] * v[j]; }
#pragma unroll
            for (int m = 1; m < 16; m <<= 1) {
                s += __shfl_xor_sync(0xffffffffu, s, m);
                q += __shfl_xor_sync(0xffffffffu, q, m);
            }
            float mu = s * (1.f / 128.f);
            float var = q * (1.f / 128.f) - mu * mu;
            float rstd = rsqrtf(var + 1e-5f);
            int n = ng8 + r;
            if (n < valid) {
                float o[8];
#pragma unroll
                for (int j = 0; j < 8; ++j) {
                    float y = (v[j] - mu) * rstd * gv[j] + bv[j];
                    o[j] = fmaxf(y, 0.f);
                }
                float* po = out + (size_t)(t0 + n) * C + c0;
                *(float4*)po       = make_float4(o[0], o[1], o[2], o[3]);
                *(float4*)(po + 4) = make_float4(o[4], o[5], o[6], o[7]);
            }
        }
    }
}

// ---------------------------------------------------------------------------
// Host launcher
// ---------------------------------------------------------------------------
extern "C" void kernel_launch(void* const* d_in, const int* in_sizes, int n_in,
                              void* d_out, int out_size) {
    const float* x_user     = (const float*)d_in[0];
    const float* x_item     = (const float*)d_in[1];
    const int*   seed_time  = (const int*)d_in[2];
    const int*   time_user  = (const int*)d_in[3];
    const int*   time_item  = (const int*)d_in[4];
    const int*   batch_user = (const int*)d_in[5];
    const int*   batch_item = (const int*)d_in[6];
    const int*   src_ui     = (const int*)d_in[7];
    const int*   dst_ui     = (const int*)d_in[8];
    const int*   src_iu     = (const int*)d_in[9];
    const int*   dst_iu     = (const int*)d_in[10];
    const float* te_W_user  = (const float*)d_in[11];
    const float* te_b_user  = (const float*)d_in[12];
    const float* te_W_item  = (const float*)d_in[13];
    const float* te_b_item  = (const float*)d_in[14];
    const float* Wl_ui      = (const float*)d_in[15];
    const float* bl_ui      = (const float*)d_in[16];
    const float* Wr_ui      = (const float*)d_in[17];
    const float* Wl_iu      = (const float*)d_in[18];
    const float* bl_iu      = (const float*)d_in[19];
    const float* Wr_iu      = (const float*)d_in[20];
    const float* ln_g_user  = (const float*)d_in[21];
    const float* ln_b_user  = (const float*)d_in[22];
    const float* ln_g_item  = (const float*)d_in[23];
    const float* ln_b_item  = (const float*)d_in[24];
    float* outp = (float*)d_out;

    const int E = in_sizes[7];

    float *xu, *xi;
    int *cntu, *cnti, *offu, *offi, *curu, *curi, *csrui, *csriu, *bsum;
    cudaGetSymbolAddress((void**)&xu,    g_xu);
    cudaGetSymbolAddress((void**)&xi,    g_xi);
    cudaGetSymbolAddress((void**)&cntu,  g_cnt_u);
    cudaGetSymbolAddress((void**)&cnti,  g_cnt_i);
    cudaGetSymbolAddress((void**)&offu,  g_off_u);
    cudaGetSymbolAddress((void**)&offi,  g_off_i);
    cudaGetSymbolAddress((void**)&curu,  g_cur_u);
    cudaGetSymbolAddress((void**)&curi,  g_cur_i);
    cudaGetSymbolAddress((void**)&csrui, g_csr_ui);
    cudaGetSymbolAddress((void**)&csriu, g_csr_iu);
    cudaGetSymbolAddress((void**)&bsum,  g_bsum);
    float* xu0 = xu;
    float* xu1 = xu + (size_t)NU * C;
    float* xi0 = xi;
    float* xi1 = xi + (size_t)NI * C;

    const int UPD_SMEM = UPD_SMEM_FLOATS * 4;
    const int TE_SMEM  = TE_SMEM_FLOATS * 4;
    cudaFuncSetAttribute(update_kernel,   cudaFuncAttributeMaxDynamicSharedMemorySize, UPD_SMEM);
    cudaFuncSetAttribute(temporal_kernel, cudaFuncAttributeMaxDynamicSharedMemorySize, TE_SMEM);

    const int NSM = 148;

    // --- CSR build (dst arrays are layer-invariant: build once, use twice) ---
    zero_int_kernel<<<256, 256>>>((int4*)cntu, NU / 4);
    zero_int_kernel<<<256, 256>>>((int4*)cnti, NI / 4);
    count_kernel<<<2048, 256>>>(dst_ui, cnti, E);
    count_kernel<<<2048, 256>>>(dst_iu, cntu, E);

    int nbi = (NI + SCAN_CHUNK - 1) / SCAN_CHUNK;
    int nbu = (NU + SCAN_CHUNK - 1) / SCAN_CHUNK;
    scan_pass1<<<nbi, 256>>>(cnti, bsum, NI);
    scan_pass2<<<1, 32>>>(bsum, nbi);
    scan_pass3<<<nbi, 256>>>(cnti, bsum, offi, curi, NI);
    scan_pass1<<<nbu, 256>>>(cntu, bsum, NU);
    scan_pass2<<<1, 32>>>(bsum, nbu);
    scan_pass3<<<nbu, 256>>>(cntu, bsum, offu, curu, NU);

    fill_kernel<<<2048, 256>>>(src_ui, dst_ui, curi, csrui, E);
    fill_kernel<<<2048, 256>>>(src_iu, dst_iu, curu, csriu, E);

    // --- temporal encoder ---
    temporal_kernel<<<NSM, 256, TE_SMEM>>>(x_user, seed_time, time_user, batch_user,
                                           te_W_user, te_b_user, xu0, NU);
    temporal_kernel<<<NSM, 256, TE_SMEM>>>(x_item, seed_time, time_item, batch_item,
                                           te_W_item, te_b_item, xi0, NI);

    const float* cu = xu0;
    const float* ci = xi0;
    for (int l = 0; l < 2; ++l) {
        float* oi = (l == 1) ? (outp + (size_t)NU * C) : xi1;
        float* ou = (l == 1) ? outp : xu1;
        // items aggregate USER features over csr_ui
        update_kernel<<<NSM, 256, UPD_SMEM>>>(cu, csrui, offi, ci,
                                              Wl_ui + (size_t)l * CC, Wr_ui + (size_t)l * CC,
                                              bl_ui + (size_t)l * C,
                                              ln_g_item + (size_t)l * C, ln_b_item + (size_t)l * C,
                                              oi, NI);
        // users aggregate ITEM features over csr_iu (reads old ci — double buffered)
        update_kernel<<<NSM, 256, UPD_SMEM>>>(ci, csriu, offu, cu,
                                              Wl_iu + (size_t)l * CC, Wr_iu + (size_t)l * CC,
                                              bl_iu + (size_t)l * C,
                                              ln_g_user + (size_t)l * C, ln_b_user + (size_t)l * C,
                                              ou, NU);
        cu = xu1;
        ci = xi1;
    }
}

// round 4
// speedup vs baseline: 1.4159x; 1.4159x over previous
#include <cuda_runtime.h>
#include <cstdint>
#include <cstddef>

#define C 128
#define CC (C * C)
#define NU 100000
#define NI 200000
#define NEDGE 1500000

// ---------------------------------------------------------------------------
// Scratch (device globals; no runtime allocation allowed)
// ---------------------------------------------------------------------------
__device__ __align__(256) float g_xu[2][(size_t)NU * C];
__device__ __align__(256) float g_xi[2][(size_t)NI * C];
__device__ __align__(256) float g_msg_u[(size_t)NU * C];
__device__ __align__(256) float g_msg_i[(size_t)NI * C];
__device__ __align__(256) int   g_cnt_u[NU];
__device__ __align__(256) int   g_cnt_i[NI];
__device__ __align__(256) int   g_off_u[NU + 1];
__device__ __align__(256) int   g_off_i[NI + 1];
__device__ __align__(256) int   g_cur_u[NU];
__device__ __align__(256) int   g_cur_i[NI];
__device__ __align__(256) int   g_csr_ui[NEDGE];  // src(user) ids grouped by dst item
__device__ __align__(256) int   g_csr_iu[NEDGE];  // src(item) ids grouped by dst user
__device__ __align__(256) int   g_bsum[256];

// ---------------------------------------------------------------------------
// f32x2 helpers (Blackwell packed fp32: 2x FFMA throughput vs 3-reg FFMA)
// ---------------------------------------------------------------------------
__device__ __forceinline__ unsigned long long pack2(float x, float y) {
    unsigned long long r;
    asm("mov.b64 %0, {%1, %2};" : "=l"(r) : "f"(x), "f"(y));
    return r;
}
__device__ __forceinline__ void unpack2(unsigned long long v, float& x, float& y) {
    asm("mov.b64 {%0, %1}, %2;" : "=f"(x), "=f"(y) : "l"(v));
}
__device__ __forceinline__ void ffma2(unsigned long long& d, unsigned long long a,
                                      unsigned long long b) {
    asm("fma.rn.f32x2 %0, %1, %2, %0;" : "+l"(d) : "l"(a), "l"(b));
}
__device__ __forceinline__ float f4get(float4 v, int i) {
    return i == 0 ? v.x : (i == 1 ? v.y : (i == 2 ? v.z : v.w));
}
__device__ __forceinline__ void add4(float4& a, float4 b) {
    a.x += b.x; a.y += b.y; a.z += b.z; a.w += b.w;
}

// Shared-memory strides (pad 132 floats: 16B-aligned rows, reduced conflicts)
#define SROW 132
#define UPD_SMEM_FLOATS (256 * SROW + 128 * SROW)
#define TE_SMEM_FLOATS  (128 * SROW * 2 + 128 + 64)

// One 128-wide K phase: acc[8][4] += In[node][k] * Wt[k][chan]
__device__ __forceinline__ void mac_phase(const float* sW, const float* sIn,
                                          int ng8, int c0,
                                          unsigned long long acc[8][4]) {
#pragma unroll 1
    for (int kc = 0; kc < 128; kc += 4) {
        float4 a4[8];
#pragma unroll
        for (int r = 0; r < 8; ++r)
            a4[r] = *(const float4*)(sIn + (ng8 + r) * SROW + kc);
#pragma unroll
        for (int kk = 0; kk < 4; ++kk) {
            const float* wr = sW + (kc + kk) * SROW + c0;
            ulonglong2 w01 = *(const ulonglong2*)(wr);
            ulonglong2 w23 = *(const ulonglong2*)(wr + 4);
#pragma unroll
            for (int r = 0; r < 8; ++r) {
                float av = f4get(a4[r], kk);
                unsigned long long a2 = pack2(av, av);
                ffma2(acc[r][0], a2, w01.x);
                ffma2(acc[r][1], a2, w01.y);
                ffma2(acc[r][2], a2, w23.x);
                ffma2(acc[r][3], a2, w23.y);
            }
        }
    }
}

// ---------------------------------------------------------------------------
// CSR build kernels
// ---------------------------------------------------------------------------
__global__ void zero_int_kernel(int4* __restrict__ p, int n4) {
    int stride = gridDim.x * blockDim.x;
    for (int i = blockIdx.x * blockDim.x + threadIdx.x; i < n4; i += stride)
        p[i] = make_int4(0, 0, 0, 0);
}

__global__ void count_kernel(const int* __restrict__ dst, int* __restrict__ cnt, int nE) {
    int stride = gridDim.x * blockDim.x;
    for (int i = blockIdx.x * blockDim.x + threadIdx.x; i < nE; i += stride)
        atomicAdd(cnt + __ldg(dst + i), 1);
}

#define SCAN_CHUNK 2048  // 256 threads x 8 elements

__global__ void scan_pass1(const int* __restrict__ cnt, int* __restrict__ bsum, int n) {
    __shared__ int sh[256];
    int tid = threadIdx.x;
    int base = blockIdx.x * SCAN_CHUNK + tid * 8;
    int s = 0;
#pragma unroll
    for (int j = 0; j < 8; ++j) {
        int idx = base + j;
        if (idx < n) s += cnt[idx];
    }
    sh[tid] = s;
    __syncthreads();
    for (int m = 128; m > 0; m >>= 1) {
        if (tid < m) sh[tid] += sh[tid + m];
        __syncthreads();
    }
    if (tid == 0) bsum[blockIdx.x] = sh[0];
}

__global__ void scan_pass2(int* __restrict__ bsum, int nb) {
    if (threadIdx.x == 0 && blockIdx.x == 0) {
        int acc = 0;
        for (int i = 0; i < nb; ++i) {
            int v = bsum[i];
            bsum[i] = acc;
            acc += v;
        }
    }
}

__global__ void scan_pass3(const int* __restrict__ cnt, const int* __restrict__ bsum,
                           int* __restrict__ off, int* __restrict__ cur, int n) {
    __shared__ int wsum[8];
    int tid = threadIdx.x;
    int lane = tid & 31, wrp = tid >> 5;
    int base = blockIdx.x * SCAN_CHUNK + tid * 8;

    int val[8], loc[8];
    int s = 0;
#pragma unroll
    for (int j = 0; j < 8; ++j) {
        int idx = base + j;
        val[j] = (idx < n) ? cnt[idx] : 0;
        loc[j] = s;
        s += val[j];
    }
    int incl = s;
#pragma unroll
    for (int m = 1; m < 32; m <<= 1) {
        int t = __shfl_up_sync(0xffffffffu, incl, m);
        if (lane >= m) incl += t;
    }
    if (lane == 31) wsum[wrp] = incl;
    __syncthreads();
    if (tid == 0) {
        int acc = 0;
#pragma unroll
        for (int i = 0; i < 8; ++i) {
            int t = wsum[i];
            wsum[i] = acc;
            acc += t;
        }
    }
    __syncthreads();
    int excl = incl - s + wsum[wrp];
    int boff = bsum[blockIdx.x];
#pragma unroll
    for (int j = 0; j < 8; ++j) {
        int idx = base + j;
        if (idx < n) {
            int o = boff + excl + loc[j];
            off[idx] = o;
            cur[idx] = o;
            if (idx == n - 1) off[n] = o + val[j];
        }
    }
}

__global__ void fill_kernel(const int* __restrict__ src, const int* __restrict__ dst,
                            int* __restrict__ cur, int* __restrict__ csr, int nE) {
    int stride = gridDim.x * blockDim.x;
    for (int i = blockIdx.x * blockDim.x + threadIdx.x; i < nE; i += stride) {
        int d = __ldg(dst + i);
        int p = atomicAdd(cur + d, 1);
        csr[p] = __ldg(src + i);
    }
}

// ---------------------------------------------------------------------------
// CSR gather-mean: msg[n] = mean over neighbors of x_src  (warp per node,
// high occupancy, no atomics, no zero-init; x_src rows mostly hit L2)
// ---------------------------------------------------------------------------
__global__ __launch_bounds__(256)
void gather_kernel(const float* __restrict__ x_src, const int* __restrict__ csr,
                   const int* __restrict__ off, float* __restrict__ msg, int n_dst) {
    int lane = threadIdx.x & 31;
    int w = (blockIdx.x * blockDim.x + threadIdx.x) >> 5;
    int nW = (gridDim.x * blockDim.x) >> 5;
    for (int n = w; n < n_dst; n += nW) {
        int o0 = __ldg(off + n);
        int o1 = __ldg(off + n + 1);
        int deg = o1 - o0;
        float4 a0 = make_float4(0.f, 0.f, 0.f, 0.f);
        float4 a1 = a0, a2 = a0, a3 = a0;
        int k = o0;
        for (; k + 4 <= o1; k += 4) {
            int s0 = __ldg(csr + k);
            int s1 = __ldg(csr + k + 1);
            int s2 = __ldg(csr + k + 2);
            int s3 = __ldg(csr + k + 3);
            add4(a0, __ldg((const float4*)(x_src + (size_t)s0 * C) + lane));
            add4(a1, __ldg((const float4*)(x_src + (size_t)s1 * C) + lane));
            add4(a2, __ldg((const float4*)(x_src + (size_t)s2 * C) + lane));
            add4(a3, __ldg((const float4*)(x_src + (size_t)s3 * C) + lane));
        }
        for (; k < o1; ++k) {
            int s0 = __ldg(csr + k);
            add4(a0, __ldg((const float4*)(x_src + (size_t)s0 * C) + lane));
        }
        add4(a0, a1); add4(a2, a3); add4(a0, a2);
        float invd = 1.0f / (float)max(deg, 1);
        a0.x *= invd; a0.y *= invd; a0.z *= invd; a0.w *= invd;
        *((float4*)(msg + (size_t)n * C) + lane) = a0;
    }
}

// ---------------------------------------------------------------------------
// Temporal encoder: out = x + PE(rel_time) @ W^T + b
// ---------------------------------------------------------------------------
__global__ __launch_bounds__(256, 1)
void temporal_kernel(const float* __restrict__ x, const int* __restrict__ seed_time,
                     const int* __restrict__ node_time, const int* __restrict__ batch,
                     const float* __restrict__ W, const float* __restrict__ bias,
                     float* __restrict__ out, int n_nodes) {
    extern __shared__ float smem[];
    float* sW   = smem;                    // [128][SROW]
    float* sPE  = smem + 128 * SROW;       // [128][SROW]
    float* sRel = sPE + 128 * SROW;        // [128]
    float* sDiv = sRel + 128;              // [64]

    int tid = threadIdx.x;
    int cg = tid & 15, ng = tid >> 4;
    int c0 = cg * 8, ng8 = ng * 8;

    for (int i = tid; i < CC; i += 256) {
        int c = i >> 7, k = i & 127;
        sW[k * SROW + c] = W[i];
    }
    if (tid < 64)
        sDiv[tid] = exp2f(-(float)tid * 0.20762050593046015f);  // 10000^(-j/64)

    unsigned long long bias2[4];
#pragma unroll
    for (int p = 0; p < 4; ++p)
        bias2[p] = pack2(__ldg(bias + c0 + 2 * p), __ldg(bias + c0 + 2 * p + 1));
    __syncthreads();

    int ntiles = (n_nodes + 127) >> 7;
    for (int t = blockIdx.x; t < ntiles; t += gridDim.x) {
        int t0 = t << 7;
        int valid = min(128, n_nodes - t0);
        __syncthreads();

        if (tid < 128) {
            float r = 0.f;
            int n = t0 + tid;
            if (tid < valid) {
                int st = __ldg(seed_time + __ldg(batch + n));
                r = (float)(st - __ldg(node_time + n)) * (1.0f / 86400.0f);
            }
            sRel[tid] = r;
        }
        __syncthreads();

        for (int i = tid; i < 128 * 64; i += 256) {
            int n = i >> 6, j = i & 63;
            float ang = sRel[n] * sDiv[j];
            float kq = rintf(ang * 0.15915494309189535f);
            ang = fmaf(kq, -6.283185307179586f, ang);
            float sv, cv;
            sincosf(ang, &sv, &cv);
            sPE[n * SROW + 2 * j]     = sv;
            sPE[n * SROW + 2 * j + 1] = cv;
        }
        __syncthreads();

        unsigned long long acc[8][4];
#pragma unroll
        for (int r = 0; r < 8; ++r)
#pragma unroll
            for (int p = 0; p < 4; ++p) acc[r][p] = bias2[p];

        mac_phase(sW, sPE, ng8, c0, acc);

#pragma unroll
        for (int r = 0; r < 8; ++r) {
            int n = ng8 + r;
            if (n < valid) {
                float v[8];
#pragma unroll
                for (int p = 0; p < 4; ++p) unpack2(acc[r][p], v[2 * p], v[2 * p + 1]);
                const float* px = x + (size_t)(t0 + n) * C + c0;
                float4 x0 = __ldg((const float4*)px);
                float4 x1 = __ldg((const float4*)px + 1);
                float* po = out + (size_t)(t0 + n) * C + c0;
                *(float4*)po = make_float4(v[0] + x0.x, v[1] + x0.y, v[2] + x0.z, v[3] + x0.w);
                *(float4*)(po + 4) = make_float4(v[4] + x1.x, v[5] + x1.y, v[6] + x1.z, v[7] + x1.w);
            }
        }
    }
}

// ---------------------------------------------------------------------------
// Layer update: out = relu(LN(msg @ Wl^T + bias + x @ Wr^T))   (msg pre-averaged)
// ---------------------------------------------------------------------------
__global__ __launch_bounds__(256, 1)
void update_kernel(const float* __restrict__ msg,
                   const float* __restrict__ xin,
                   const float* __restrict__ Wl, const float* __restrict__ Wr,
                   const float* __restrict__ bias,
                   const float* __restrict__ lng, const float* __restrict__ lnb,
                   float* __restrict__ out, int n_nodes) {
    extern __shared__ float smem[];
    float* sW  = smem;               // [256][SROW]: rows 0..127 = Wl^T, 128..255 = Wr^T
    float* sIn = smem + 256 * SROW;  // [128][SROW]

    int tid = threadIdx.x;
    int cg = tid & 15, ng = tid >> 4;
    int c0 = cg * 8, ng8 = ng * 8;

    for (int i = tid; i < CC; i += 256) {
        int c = i >> 7, k = i & 127;
        sW[k * SROW + c]         = Wl[i];
        sW[(128 + k) * SROW + c] = Wr[i];
    }
    float gv[8], bv[8];
    unsigned long long bias2[4];
#pragma unroll
    for (int j = 0; j < 8; ++j) {
        gv[j] = __ldg(lng + c0 + j);
        bv[j] = __ldg(lnb + c0 + j);
    }
#pragma unroll
    for (int p = 0; p < 4; ++p)
        bias2[p] = pack2(__ldg(bias + c0 + 2 * p), __ldg(bias + c0 + 2 * p + 1));
    __syncthreads();

    int ntiles = (n_nodes + 127) >> 7;
    for (int t = blockIdx.x; t < ntiles; t += gridDim.x) {
        int t0 = t << 7;
        int valid = min(128, n_nodes - t0);

        unsigned long long acc[8][4];
#pragma unroll
        for (int r = 0; r < 8; ++r)
#pragma unroll
            for (int p = 0; p < 4; ++p) acc[r][p] = bias2[p];

        // phase 0: aggregated neighbor features (already averaged)
        for (int i = tid; i < 128 * 32; i += 256) {
            int n = i >> 5, c4 = (i & 31) << 2;
            float4 v = make_float4(0.f, 0.f, 0.f, 0.f);
            if (n < valid)
                v = __ldg((const float4*)(msg + (size_t)(t0 + n) * C + c4));
            *(float4*)(sIn + n * SROW + c4) = v;
        }
        __syncthreads();
        mac_phase(sW, sIn, ng8, c0, acc);
        __syncthreads();

        // phase 1: self features
        for (int i = tid; i < 128 * 32; i += 256) {
            int n = i >> 5, c4 = (i & 31) << 2;
            float4 v = make_float4(0.f, 0.f, 0.f, 0.f);
            if (n < valid)
                v = __ldg((const float4*)(xin + (size_t)(t0 + n) * C + c4));
            *(float4*)(sIn + n * SROW + c4) = v;
        }
        __syncthreads();
        mac_phase(sW + 128 * SROW, sIn, ng8, c0, acc);
        __syncthreads();

        // epilogue: LayerNorm (reduce across the 16 channel-group lanes) + ReLU
#pragma unroll
        for (int r = 0; r < 8; ++r) {
            float v[8];
#pragma unroll
            for (int p = 0; p < 4; ++p) unpack2(acc[r][p], v[2 * p], v[2 * p + 1]);
            float s = 0.f, q = 0.f;
#pragma unroll
            for (int j = 0; j < 8; ++j) { s += v[j]; q += v[j] * v[j]; }
#pragma unroll
            for (int m = 1; m < 16; m <<= 1) {
                s += __shfl_xor_sync(0xffffffffu, s, m);
                q += __shfl_xor_sync(0xffffffffu, q, m);
            }
            float mu = s * (1.f / 128.f);
            float var = q * (1.f / 128.f) - mu * mu;
            float rstd = rsqrtf(var + 1e-5f);
            int n = ng8 + r;
            if (n < valid) {
                float o[8];
#pragma unroll
                for (int j = 0; j < 8; ++j) {
                    float y = (v[j] - mu) * rstd * gv[j] + bv[j];
                    o[j] = fmaxf(y, 0.f);
                }
                float* po = out + (size_t)(t0 + n) * C + c0;
                *(float4*)po       = make_float4(o[0], o[1], o[2], o[3]);
                *(float4*)(po + 4) = make_float4(o[4], o[5], o[6], o[7]);
            }
        }
    }
}

// ---------------------------------------------------------------------------
// Host launcher
// ---------------------------------------------------------------------------
extern "C" void kernel_launch(void* const* d_in, const int* in_sizes, int n_in,
                              void* d_out, int out_size) {
    const float* x_user     = (const float*)d_in[0];
    const float* x_item     = (const float*)d_in[1];
    const int*   seed_time  = (const int*)d_in[2];
    const int*   time_user  = (const int*)d_in[3];
    const int*   time_item  = (const int*)d_in[4];
    const int*   batch_user = (const int*)d_in[5];
    const int*   batch_item = (const int*)d_in[6];
    const int*   src_ui     = (const int*)d_in[7];
    const int*   dst_ui     = (const int*)d_in[8];
    const int*   src_iu     = (const int*)d_in[9];
    const int*   dst_iu     = (const int*)d_in[10];
    const float* te_W_user  = (const float*)d_in[11];
    const float* te_b_user  = (const float*)d_in[12];
    const float* te_W_item  = (const float*)d_in[13];
    const float* te_b_item  = (const float*)d_in[14];
    const float* Wl_ui      = (const float*)d_in[15];
    const float* bl_ui      = (const float*)d_in[16];
    const float* Wr_ui      = (const float*)d_in[17];
    const float* Wl_iu      = (const float*)d_in[18];
    const float* bl_iu      = (const float*)d_in[19];
    const float* Wr_iu      = (const float*)d_in[20];
    const float* ln_g_user  = (const float*)d_in[21];
    const float* ln_b_user  = (const float*)d_in[22];
    const float* ln_g_item  = (const float*)d_in[23];
    const float* ln_b_item  = (const float*)d_in[24];
    float* outp = (float*)d_out;

    const int E = in_sizes[7];

    float *xu, *xi, *msgu, *msgi;
    int *cntu, *cnti, *offu, *offi, *curu, *curi, *csrui, *csriu, *bsum;
    cudaGetSymbolAddress((void**)&xu,    g_xu);
    cudaGetSymbolAddress((void**)&xi,    g_xi);
    cudaGetSymbolAddress((void**)&msgu,  g_msg_u);
    cudaGetSymbolAddress((void**)&msgi,  g_msg_i);
    cudaGetSymbolAddress((void**)&cntu,  g_cnt_u);
    cudaGetSymbolAddress((void**)&cnti,  g_cnt_i);
    cudaGetSymbolAddress((void**)&offu,  g_off_u);
    cudaGetSymbolAddress((void**)&offi,  g_off_i);
    cudaGetSymbolAddress((void**)&curu,  g_cur_u);
    cudaGetSymbolAddress((void**)&curi,  g_cur_i);
    cudaGetSymbolAddress((void**)&csrui, g_csr_ui);
    cudaGetSymbolAddress((void**)&csriu, g_csr_iu);
    cudaGetSymbolAddress((void**)&bsum,  g_bsum);
    float* xu0 = xu;
    float* xu1 = xu + (size_t)NU * C;
    float* xi0 = xi;
    float* xi1 = xi + (size_t)NI * C;

    const int UPD_SMEM = UPD_SMEM_FLOATS * 4;
    const int TE_SMEM  = TE_SMEM_FLOATS * 4;
    cudaFuncSetAttribute(update_kernel,   cudaFuncAttributeMaxDynamicSharedMemorySize, UPD_SMEM);
    cudaFuncSetAttribute(temporal_kernel, cudaFuncAttributeMaxDynamicSharedMemorySize, TE_SMEM);

    const int NSM = 148;

    // --- CSR build (dst arrays are layer-invariant: build once, use twice) ---
    zero_int_kernel<<<256, 256>>>((int4*)cntu, NU / 4);
    zero_int_kernel<<<256, 256>>>((int4*)cnti, NI / 4);
    count_kernel<<<2048, 256>>>(dst_ui, cnti, E);
    count_kernel<<<2048, 256>>>(dst_iu, cntu, E);

    int nbi = (NI + SCAN_CHUNK - 1) / SCAN_CHUNK;
    int nbu = (NU + SCAN_CHUNK - 1) / SCAN_CHUNK;
    scan_pass1<<<nbi, 256>>>(cnti, bsum, NI);
    scan_pass2<<<1, 32>>>(bsum, nbi);
    scan_pass3<<<nbi, 256>>>(cnti, bsum, offi, curi, NI);
    scan_pass1<<<nbu, 256>>>(cntu, bsum, NU);
    scan_pass2<<<1, 32>>>(bsum, nbu);
    scan_pass3<<<nbu, 256>>>(cntu, bsum, offu, curu, NU);

    fill_kernel<<<2048, 256>>>(src_ui, dst_ui, curi, csrui, E);
    fill_kernel<<<2048, 256>>>(src_iu, dst_iu, curu, csriu, E);

    // --- temporal encoder ---
    temporal_kernel<<<NSM, 256, TE_SMEM>>>(x_user, seed_time, time_user, batch_user,
                                           te_W_user, te_b_user, xu0, NU);
    temporal_kernel<<<NSM, 256, TE_SMEM>>>(x_item, seed_time, time_item, batch_item,
                                           te_W_item, te_b_item, xi0, NI);

    const float* cu = xu0;
    const float* ci = xi0;
    for (int l = 0; l < 2; ++l) {
        // high-occupancy CSR gather (no atomics, mean folded in)
        gather_kernel<<<2048, 256>>>(cu, csrui, offi, msgi, NI);
        gather_kernel<<<2048, 256>>>(ci, csriu, offu, msgu, NU);

        float* oi = (l == 1) ? (outp + (size_t)NU * C) : xi1;
        float* ou = (l == 1) ? outp : xu1;
        update_kernel<<<NSM, 256, UPD_SMEM>>>(msgi, ci,
                                              Wl_ui + (size_t)l * CC, Wr_ui + (size_t)l * CC,
                                              bl_ui + (size_t)l * C,
                                              ln_g_item + (size_t)l * C, ln_b_item + (size_t)l * C,
                                              oi, NI);
        update_kernel<<<NSM, 256, UPD_SMEM>>>(msgu, cu,
                                              Wl_iu + (size_t)l * CC, Wr_iu + (size_t)l * CC,
                                              bl_iu + (size_t)l * C,
                                              ln_g_user + (size_t)l * C, ln_b_user + (size_t)l * C,
                                              ou, NU);
        cu = xu1;
        ci = xi1;
    }
}